// round 1
// baseline (speedup 1.0000x reference)
#include <cuda_runtime.h>
#include <cstdint>
#include <cstddef>

#define Bsz 128
#define Ssz 1024
#define Dsz 256
#define Hsz 256
#define G3  768

// 402 MB scratch for precomputed input gates gx = x @ W_ih + b_ih
__device__ float g_gx[(size_t)Bsz * Ssz * G3];

// ---------------------------------------------------------------------------
// Kernel A: gx[M=131072, 768] = X[M,256] @ W_ih[256,768] + b_ih
// 128x128 block tile, BK=16, 256 threads, 8x8 microtile.
// ---------------------------------------------------------------------------
__global__ __launch_bounds__(256) void gemm_gx_kernel(
    const float* __restrict__ X, const float* __restrict__ W,
    const float* __restrict__ bias)
{
    __shared__ float As[16][128];   // [k][row] (A transposed in smem)
    __shared__ float Bs[16][128];   // [k][col]

    const int tid  = threadIdx.x;
    const int brow = blockIdx.y * 128;
    const int bcol = blockIdx.x * 128;
    const int ty   = tid >> 4;
    const int tx   = tid & 15;

    float acc[8][8];
#pragma unroll
    for (int i = 0; i < 8; i++)
#pragma unroll
        for (int j = 0; j < 8; j++) acc[i][j] = 0.f;

    for (int k0 = 0; k0 < Dsz; k0 += 16) {
#pragma unroll
        for (int it = 0; it < 2; it++) {
            int id = tid + it * 256;
            int arow = id >> 2;
            int ak   = (id & 3) << 2;
            float4 av = *reinterpret_cast<const float4*>(
                &X[(size_t)(brow + arow) * Dsz + k0 + ak]);
            As[ak + 0][arow] = av.x;
            As[ak + 1][arow] = av.y;
            As[ak + 2][arow] = av.z;
            As[ak + 3][arow] = av.w;
            int bk = id >> 5;
            int bc = (id & 31) << 2;
            *reinterpret_cast<float4*>(&Bs[bk][bc]) =
                *reinterpret_cast<const float4*>(&W[(size_t)(k0 + bk) * G3 + bcol + bc]);
        }
        __syncthreads();
#pragma unroll
        for (int kk = 0; kk < 16; kk++) {
            float ra[8], rb[8];
            *reinterpret_cast<float4*>(&ra[0]) = *reinterpret_cast<float4*>(&As[kk][ty * 8]);
            *reinterpret_cast<float4*>(&ra[4]) = *reinterpret_cast<float4*>(&As[kk][ty * 8 + 4]);
            *reinterpret_cast<float4*>(&rb[0]) = *reinterpret_cast<float4*>(&Bs[kk][tx * 8]);
            *reinterpret_cast<float4*>(&rb[4]) = *reinterpret_cast<float4*>(&Bs[kk][tx * 8 + 4]);
#pragma unroll
            for (int i = 0; i < 8; i++)
#pragma unroll
                for (int j = 0; j < 8; j++)
                    acc[i][j] = fmaf(ra[i], rb[j], acc[i][j]);
        }
        __syncthreads();
    }

#pragma unroll
    for (int i = 0; i < 8; i++) {
        int row = brow + ty * 8 + i;
#pragma unroll
        for (int j = 0; j < 8; j += 4) {
            int col = bcol + tx * 8 + j;
            float4 bv = *reinterpret_cast<const float4*>(&bias[col]);
            float4 cv;
            cv.x = acc[i][j + 0] + bv.x;
            cv.y = acc[i][j + 1] + bv.y;
            cv.z = acc[i][j + 2] + bv.z;
            cv.w = acc[i][j + 3] + bv.w;
            *reinterpret_cast<float4*>(&g_gx[(size_t)row * G3 + col]) = cv;
        }
    }
}

// ---------------------------------------------------------------------------
// Kernel B: persistent GRU recurrence.
// Cluster of 4 CTAs per 4 batch rows. CTA rank r owns hidden slice
// j in [64r, 64r+64) and keeps W_hh[:, {j, 256+j, 512+j}] (192 KB) in SMEM.
// Each step: column-split gh GEMM -> smem reduce over 8 k-eighths ->
// elementwise gates -> distribute 64-float h slice to all 4 CTAs via DSMEM
// -> one cluster barrier (double-buffered h).
// ---------------------------------------------------------------------------
#define TPB_B 512
#define KLEN  32      // k-range per thread group (8 groups cover K=256)

// smem layout (floats): Ws[256*192] | hb[2][4][256] | red[8][4][3][64]
#define SMF_W   0
#define SMF_H   (256 * 192)
#define SMF_RED (SMF_W + 256 * 192 + 2 * 4 * 256)
#define SMF_TOT (SMF_RED + 8 * 4 * 3 * 64)
#define SMEM_B_BYTES (SMF_TOT * 4)

__device__ __forceinline__ float sigmoidf_fast(float x) {
    return __fdividef(1.0f, 1.0f + __expf(-x));
}
__device__ __forceinline__ float tanhf_fast(float x) {
    x = fminf(fmaxf(x, -15.f), 15.f);
    float e = __expf(2.f * x);
    return __fdividef(e - 1.f, e + 1.f);
}

__global__ void __cluster_dims__(4, 1, 1) __launch_bounds__(TPB_B, 1)
gru_rec_kernel(const float* __restrict__ mask,
               const float* __restrict__ Whh,
               const float* __restrict__ bhh,
               float* __restrict__ out)
{
    extern __shared__ float sm[];
    float* Ws  = sm + SMF_W;
    float* hb  = sm + SMF_H;
    float* red = sm + SMF_RED;

    const int tid = threadIdx.x;
    uint32_t rank;
    asm("mov.u32 %0, %%cluster_ctarank;" : "=r"(rank));
    const int ci = (int)blockIdx.x >> 2;   // cluster index 0..31

    // Stage this CTA's W_hh column slice: Ws[k*192 + g*64 + jj] =
    // Whh[k*768 + g*256 + rank*64 + jj]
    for (int idx = tid; idx < 256 * 192; idx += TPB_B) {
        int k = idx / 192;
        int c = idx - k * 192;
        int g = c >> 6;
        int j0 = c & 63;
        Ws[idx] = Whh[k * G3 + g * 256 + (int)rank * 64 + j0];
    }
    // Zero h buffer parity 0 (h0 = 0)
    for (int idx = tid; idx < 4 * 256; idx += TPB_B) hb[idx] = 0.f;

    const int kq = tid >> 6;        // 0..7 : k-eighth
    const int jj = tid & 63;        // hidden column within slice
    const int bb = kq & 3;          // batch index, valid when tid < 256
    const bool ew = (tid < 256);    // elementwise-phase threads
    const int jg = (int)rank * 64 + jj;

    float bhr = 0.f, bhz = 0.f, bhn = 0.f, hold = 0.f;
    const float* gx_p = nullptr;
    const float* m_p  = nullptr;
    float* out_p = nullptr;
    if (ew) {
        bhr = bhh[jg];
        bhz = bhh[256 + jg];
        bhn = bhh[512 + jg];
        int bbg = ci * 4 + bb;
        gx_p  = g_gx + (size_t)bbg * Ssz * G3;
        m_p   = mask + (size_t)bbg * Ssz;
        out_p = out + (size_t)bbg * Ssz * Hsz + jg;
    }

    uint32_t hb_u32;
    asm("{ .reg .u64 t; cvta.to.shared.u64 t, %1; cvt.u32.u64 %0, t; }"
        : "=r"(hb_u32) : "l"(hb));

    __syncthreads();
    asm volatile("barrier.cluster.arrive.aligned;" ::: "memory");
    asm volatile("barrier.cluster.wait.aligned;" ::: "memory");

    int par = 0;
    const int k0 = kq * KLEN;

    for (int t = 0; t < Ssz; t++) {
        // Prefetch gx + mask for this step (independent of GEMM below)
        float gxr = 0.f, gxz = 0.f, gxn = 0.f, mt = 0.f;
        if (ew) {
            const float* gxt = gx_p + (size_t)t * G3;
            gxr = __ldcs(gxt + jg);
            gxz = __ldcs(gxt + 256 + jg);
            gxn = __ldcs(gxt + 512 + jg);
            mt  = __ldg(m_p + t);
        }

        // ---- gh partial GEMM: this thread covers k in [k0, k0+32) ----
        float ar[4] = {0, 0, 0, 0}, az[4] = {0, 0, 0, 0}, an[4] = {0, 0, 0, 0};
        const float* hbase = hb + par * 1024;
#pragma unroll 2
        for (int k = k0; k < k0 + KLEN; k += 4) {
            float4 hv[4];
#pragma unroll
            for (int b2 = 0; b2 < 4; b2++)
                hv[b2] = *reinterpret_cast<const float4*>(hbase + b2 * 256 + k);
#pragma unroll
            for (int d = 0; d < 4; d++) {
                const float* wrow = Ws + (k + d) * 192;
                float wr = wrow[jj];
                float wz = wrow[64 + jj];
                float wn = wrow[128 + jj];
#pragma unroll
                for (int b2 = 0; b2 < 4; b2++) {
                    float h = reinterpret_cast<const float*>(&hv[b2])[d];
                    ar[b2] = fmaf(h, wr, ar[b2]);
                    az[b2] = fmaf(h, wz, az[b2]);
                    an[b2] = fmaf(h, wn, an[b2]);
                }
            }
        }
#pragma unroll
        for (int b2 = 0; b2 < 4; b2++) {
            int base = ((kq * 4 + b2) * 3) * 64 + jj;
            red[base]       = ar[b2];
            red[base + 64]  = az[b2];
            red[base + 128] = an[b2];
        }
        __syncthreads();

        // ---- elementwise gates + h update (first 256 threads) ----
        if (ew) {
            float ghr = bhr, ghz = bhz, ghn = bhn;
#pragma unroll
            for (int q = 0; q < 8; q++) {
                int base = ((q * 4 + bb) * 3) * 64 + jj;
                ghr += red[base];
                ghz += red[base + 64];
                ghn += red[base + 128];
            }
            hold = hbase[bb * 256 + jg];
            float r = sigmoidf_fast(gxr + ghr);
            float z = sigmoidf_fast(gxz + ghz);
            float n = tanhf_fast(fmaf(r, ghn, gxn));
            float hnew = fmaf(z, hold - n, n);           // (1-z)*n + z*hold
            float hout = fmaf(mt, hnew - hold, hold);    // m*hnew + (1-m)*hold
            out_p[(size_t)t * Hsz] = hout;

            // distribute this hidden slice element to all 4 cluster CTAs
            uint32_t laddr = hb_u32 +
                (uint32_t)((((par ^ 1) * 1024) + bb * 256 + jg) * 4);
#pragma unroll
            for (int p = 0; p < 4; p++) {
                uint32_t raddr;
                asm volatile("mapa.shared::cluster.u32 %0, %1, %2;"
                             : "=r"(raddr) : "r"(laddr), "r"(p));
                asm volatile("st.shared::cluster.f32 [%0], %1;"
                             :: "r"(raddr), "f"(hout) : "memory");
            }
        }

        asm volatile("barrier.cluster.arrive.aligned;" ::: "memory");
        asm volatile("barrier.cluster.wait.aligned;" ::: "memory");
        par ^= 1;
    }
}

// ---------------------------------------------------------------------------
extern "C" void kernel_launch(void* const* d_in, const int* in_sizes, int n_in,
                              void* d_out, int out_size)
{
    (void)in_sizes; (void)n_in; (void)out_size;
    const float* x    = (const float*)d_in[0];
    const float* mask = (const float*)d_in[1];
    const float* Wih  = (const float*)d_in[2];
    const float* Whh  = (const float*)d_in[3];
    const float* bih  = (const float*)d_in[4];
    const float* bhh  = (const float*)d_in[5];
    float* out = (float*)d_out;

    cudaFuncSetAttribute(gru_rec_kernel,
                         cudaFuncAttributeMaxDynamicSharedMemorySize,
                         SMEM_B_BYTES);

    dim3 gridA(G3 / 128, (Bsz * Ssz) / 128);
    gemm_gx_kernel<<<gridA, 256>>>(x, Wih, bih);

    gru_rec_kernel<<<Bsz, TPB_B, SMEM_B_BYTES>>>(mask, Whh, bhh, out);
}

// round 2
// speedup vs baseline: 1.0090x; 1.0090x over previous
#include <cuda_runtime.h>
#include <cstdint>
#include <cstddef>

#define Bsz 128
#define Ssz 1024
#define Dsz 256
#define Hsz 256
#define G3  768

// 402 MB scratch for precomputed input gates gx = x @ W_ih + b_ih
__device__ float g_gx[(size_t)Bsz * Ssz * G3];

typedef unsigned long long ull;

__device__ __forceinline__ ull pack2(float a) {
    ull r;
    asm("mov.b64 %0, {%1, %1};" : "=l"(r) : "f"(a));
    return r;
}
__device__ __forceinline__ void fma2(ull& acc, ull a, ull b) {
    asm("fma.rn.f32x2 %0, %1, %2, %0;" : "+l"(acc) : "l"(a), "l"(b));
}
__device__ __forceinline__ float2 unpack2(ull v) {
    float2 f;
    asm("mov.b64 {%0, %1}, %2;" : "=f"(f.x), "=f"(f.y) : "l"(v));
    return f;
}

// ---------------------------------------------------------------------------
// Kernel A: gx[M=131072, 768] = X[M,256] @ W_ih[256,768] + b_ih
// 128x128 block tile, BK=16, 256 threads, 8x8 microtile, FFMA2 math.
// ---------------------------------------------------------------------------
__global__ __launch_bounds__(256) void gemm_gx_kernel(
    const float* __restrict__ X, const float* __restrict__ W,
    const float* __restrict__ bias)
{
    __shared__ float As[16][128];   // [k][row]
    __shared__ float Bs[16][128];   // [k][col]

    const int tid  = threadIdx.x;
    const int brow = blockIdx.y * 128;
    const int bcol = blockIdx.x * 128;
    const int ty   = tid >> 4;
    const int tx   = tid & 15;

    ull acc2[8][4];   // [row i][col pair j]: lanes = cols (2j, 2j+1)
#pragma unroll
    for (int i = 0; i < 8; i++)
#pragma unroll
        for (int j = 0; j < 4; j++) acc2[i][j] = 0ull;

    for (int k0 = 0; k0 < Dsz; k0 += 16) {
#pragma unroll
        for (int it = 0; it < 2; it++) {
            int id = tid + it * 256;
            int arow = id >> 2;
            int ak   = (id & 3) << 2;
            float4 av = *reinterpret_cast<const float4*>(
                &X[(size_t)(brow + arow) * Dsz + k0 + ak]);
            As[ak + 0][arow] = av.x;
            As[ak + 1][arow] = av.y;
            As[ak + 2][arow] = av.z;
            As[ak + 3][arow] = av.w;
            int bk = id >> 5;
            int bc = (id & 31) << 2;
            *reinterpret_cast<float4*>(&Bs[bk][bc]) =
                *reinterpret_cast<const float4*>(&W[(size_t)(k0 + bk) * G3 + bcol + bc]);
        }
        __syncthreads();
#pragma unroll
        for (int kk = 0; kk < 16; kk++) {
            float ra[8];
            ull   rb2[4];
            *reinterpret_cast<float4*>(&ra[0]) = *reinterpret_cast<float4*>(&As[kk][ty * 8]);
            *reinterpret_cast<float4*>(&ra[4]) = *reinterpret_cast<float4*>(&As[kk][ty * 8 + 4]);
            ulonglong2 b01 = *reinterpret_cast<ulonglong2*>(&Bs[kk][tx * 8]);
            ulonglong2 b23 = *reinterpret_cast<ulonglong2*>(&Bs[kk][tx * 8 + 4]);
            rb2[0] = b01.x; rb2[1] = b01.y; rb2[2] = b23.x; rb2[3] = b23.y;
#pragma unroll
            for (int i = 0; i < 8; i++) {
                ull ra2 = pack2(ra[i]);
#pragma unroll
                for (int j = 0; j < 4; j++)
                    fma2(acc2[i][j], ra2, rb2[j]);
            }
        }
        __syncthreads();
    }

#pragma unroll
    for (int i = 0; i < 8; i++) {
        int row = brow + ty * 8 + i;
#pragma unroll
        for (int j2 = 0; j2 < 2; j2++) {
            int col = bcol + tx * 8 + j2 * 4;
            float4 bv = *reinterpret_cast<const float4*>(&bias[col]);
            float2 c0 = unpack2(acc2[i][j2 * 2 + 0]);
            float2 c1 = unpack2(acc2[i][j2 * 2 + 1]);
            float4 cv;
            cv.x = c0.x + bv.x;
            cv.y = c0.y + bv.y;
            cv.z = c1.x + bv.z;
            cv.w = c1.y + bv.w;
            *reinterpret_cast<float4*>(&g_gx[(size_t)row * G3 + col]) = cv;
        }
    }
}

// ---------------------------------------------------------------------------
// Kernel B: persistent GRU recurrence, FFMA2 batch-packed.
// Cluster of 4 CTAs per 4 batch rows. CTA rank r owns hidden slice
// j in [64r, 64r+64), W_hh slice (192 cols x 256 k) split: first 16 k of each
// thread's 32-k range lives in REGISTERS, rest in SMEM [kc][192][4] layout.
// h stored batch-innermost so (h_b0,h_b1) is a single 8B load.
// ---------------------------------------------------------------------------
#define TPB_B 512
#define KLEN  32

// smem floats: Ws[64][192][4] | hb[2][256][4] | red[8][2][3][64][2]
#define SMF_W   0
#define SMF_H   (64 * 192 * 4)
#define SMF_RED (SMF_H + 2 * 256 * 4)
#define SMF_TOT (SMF_RED + 8 * 2 * 3 * 64 * 2)
#define SMEM_B_BYTES (SMF_TOT * 4)

__device__ __forceinline__ float sigmoidf_fast(float x) {
    return __fdividef(1.0f, 1.0f + __expf(-x));
}
__device__ __forceinline__ float tanhf_fast(float x) {
    x = fminf(fmaxf(x, -15.f), 15.f);
    float e = __expf(2.f * x);
    return __fdividef(e - 1.f, e + 1.f);
}

__global__ void __cluster_dims__(4, 1, 1) __launch_bounds__(TPB_B, 1)
gru_rec_kernel(const float* __restrict__ mask,
               const float* __restrict__ Whh,
               const float* __restrict__ bhh,
               float* __restrict__ out)
{
    extern __shared__ float sm[];
    float* Ws  = sm + SMF_W;
    float* hb  = sm + SMF_H;
    float* red = sm + SMF_RED;

    const int tid = threadIdx.x;
    uint32_t rank;
    asm("mov.u32 %0, %%cluster_ctarank;" : "=r"(rank));
    const int ci = (int)blockIdx.x >> 2;   // cluster index 0..31

    // Stage W_hh slice into smem: Ws[(kc*192 + g*64 + jj)*4 + d] =
    //   Whh[(kc*4+d)*768 + g*256 + rank*64 + jj]
    for (int idx = tid; idx < 64 * 192 * 4; idx += TPB_B) {
        int d    = idx & 3;
        int rest = idx >> 2;        // kc*192 + c
        int kc   = rest / 192;
        int c    = rest - kc * 192;
        int g    = c >> 6;
        int j0   = c & 63;
        Ws[idx] = Whh[(kc * 4 + d) * G3 + g * 256 + (int)rank * 64 + j0];
    }
    // Zero h buffer parity 0 (h0 = 0)
    for (int idx = tid; idx < 2 * 256 * 4; idx += TPB_B) hb[idx] = 0.f;

    const int kq = tid >> 6;        // 0..7 : k-eighth
    const int jj = tid & 63;        // hidden column within slice
    const int bb = kq & 3;          // batch index (ew phase), valid tid<256
    const bool ew = (tid < 256);
    const int jg = (int)rank * 64 + jj;
    const int k0 = kq * KLEN;

    // Register-resident weights: k in [k0, k0+16), 3 gates
    float wreg[48];
#pragma unroll
    for (int kk = 0; kk < 16; kk++) {
#pragma unroll
        for (int g = 0; g < 3; g++)
            wreg[kk * 3 + g] = Whh[(k0 + kk) * G3 + g * 256 + jg];
    }

    float bhr = 0.f, bhz = 0.f, bhn = 0.f;
    const float* gx_p = nullptr;
    const float* m_p  = nullptr;
    float* out_p = nullptr;
    if (ew) {
        bhr = bhh[jg];
        bhz = bhh[256 + jg];
        bhn = bhh[512 + jg];
        int bbg = ci * 4 + bb;
        gx_p  = g_gx + (size_t)bbg * Ssz * G3;
        m_p   = mask + (size_t)bbg * Ssz;
        out_p = out + (size_t)bbg * Ssz * Hsz + jg;
    }

    uint32_t hb_u32;
    asm("{ .reg .u64 t; cvta.to.shared.u64 t, %1; cvt.u32.u64 %0, t; }"
        : "=r"(hb_u32) : "l"(hb));

    __syncthreads();
    asm volatile("barrier.cluster.arrive.aligned;" ::: "memory");
    asm volatile("barrier.cluster.wait.aligned;" ::: "memory");

    int par = 0;

    for (int t = 0; t < Ssz; t++) {
        // Prefetch gx + mask for this step (consumed after GEMM -> hidden)
        float gxr = 0.f, gxz = 0.f, gxn = 0.f, mt = 0.f;
        if (ew) {
            const float* gxt = gx_p + (size_t)t * G3;
            gxr = __ldcs(gxt + jg);
            gxz = __ldcs(gxt + 256 + jg);
            gxn = __ldcs(gxt + 512 + jg);
            mt  = __ldg(m_p + t);
        }

        // ---- gh partial GEMM: k in [k0, k0+32), batch-packed FFMA2 ----
        ull ar01 = 0, ar23 = 0, az01 = 0, az23 = 0, an01 = 0, an23 = 0;
        const float* hbK = hb + par * 1024 + k0 * 4;

        // Part 1: register weights, k offsets 0..15
#pragma unroll
        for (int c = 0; c < 4; c++) {
            ulonglong2 h[4];
#pragma unroll
            for (int d = 0; d < 4; d++)
                h[d] = *reinterpret_cast<const ulonglong2*>(hbK + (c * 4 + d) * 4);
#pragma unroll
            for (int d = 0; d < 4; d++) {
                int kk = c * 4 + d;
                ull wr2 = pack2(wreg[kk * 3 + 0]);
                ull wz2 = pack2(wreg[kk * 3 + 1]);
                ull wn2 = pack2(wreg[kk * 3 + 2]);
                fma2(ar01, h[d].x, wr2); fma2(ar23, h[d].y, wr2);
                fma2(az01, h[d].x, wz2); fma2(az23, h[d].y, wz2);
                fma2(an01, h[d].x, wn2); fma2(an23, h[d].y, wn2);
            }
        }
        // Part 2: smem weights, k offsets 16..31 (kc quads 4..7)
#pragma unroll
        for (int c = 4; c < 8; c++) {
            int kc = (k0 >> 2) + c;
            const float* wbase = Ws + (kc * 192 + jj) * 4;
            float4 w4[3];
#pragma unroll
            for (int g = 0; g < 3; g++)
                w4[g] = *reinterpret_cast<const float4*>(wbase + g * 64 * 4);
            ulonglong2 h[4];
#pragma unroll
            for (int d = 0; d < 4; d++)
                h[d] = *reinterpret_cast<const ulonglong2*>(hbK + (c * 4 + d) * 4);
#pragma unroll
            for (int d = 0; d < 4; d++) {
                const float* wr_f = &w4[0].x;
                const float* wz_f = &w4[1].x;
                const float* wn_f = &w4[2].x;
                ull wr2 = pack2(wr_f[d]);
                ull wz2 = pack2(wz_f[d]);
                ull wn2 = pack2(wn_f[d]);
                fma2(ar01, h[d].x, wr2); fma2(ar23, h[d].y, wr2);
                fma2(az01, h[d].x, wz2); fma2(az23, h[d].y, wz2);
                fma2(an01, h[d].x, wn2); fma2(an23, h[d].y, wn2);
            }
        }

        // Store partials: red[kq][p][g][jj][2], conflict-free STS.64
        {
            float* rbase = red + ((kq * 2 + 0) * 3) * 128 + jj * 2;
            *reinterpret_cast<ull*>(rbase + 0 * 128) = ar01;
            *reinterpret_cast<ull*>(rbase + 1 * 128) = az01;
            *reinterpret_cast<ull*>(rbase + 2 * 128) = an01;
            rbase += 3 * 128;   // p = 1
            *reinterpret_cast<ull*>(rbase + 0 * 128) = ar23;
            *reinterpret_cast<ull*>(rbase + 1 * 128) = az23;
            *reinterpret_cast<ull*>(rbase + 2 * 128) = an23;
        }
        __syncthreads();

        // ---- elementwise gates + h update (first 256 threads) ----
        if (ew) {
            float ghr = bhr, ghz = bhz, ghn = bhn;
            const int lane = bb & 1;
            const int p    = bb >> 1;
#pragma unroll
            for (int q = 0; q < 8; q++) {
                const float* rbase = red + ((q * 2 + p) * 3) * 128 + jj * 2 + lane;
                ghr += rbase[0 * 128];
                ghz += rbase[1 * 128];
                ghn += rbase[2 * 128];
            }
            float hold = hb[par * 1024 + jg * 4 + bb];
            float r = sigmoidf_fast(gxr + ghr);
            float z = sigmoidf_fast(gxz + ghz);
            float n = tanhf_fast(fmaf(r, ghn, gxn));
            float hnew = fmaf(z, hold - n, n);           // (1-z)*n + z*hold
            float hout = fmaf(mt, hnew - hold, hold);    // m*hnew + (1-m)*hold
            out_p[(size_t)t * Hsz] = hout;

            // distribute to all 4 cluster CTAs (hb[par^1][jg][bb])
            uint32_t laddr = hb_u32 +
                (uint32_t)((((par ^ 1) * 1024) + jg * 4 + bb) * 4);
#pragma unroll
            for (int pp = 0; pp < 4; pp++) {
                uint32_t raddr;
                asm volatile("mapa.shared::cluster.u32 %0, %1, %2;"
                             : "=r"(raddr) : "r"(laddr), "r"(pp));
                asm volatile("st.shared::cluster.f32 [%0], %1;"
                             :: "r"(raddr), "f"(hout) : "memory");
            }
        }

        asm volatile("barrier.cluster.arrive.aligned;" ::: "memory");
        asm volatile("barrier.cluster.wait.aligned;" ::: "memory");
        par ^= 1;
    }
}

// ---------------------------------------------------------------------------
extern "C" void kernel_launch(void* const* d_in, const int* in_sizes, int n_in,
                              void* d_out, int out_size)
{
    (void)in_sizes; (void)n_in; (void)out_size;
    const float* x    = (const float*)d_in[0];
    const float* mask = (const float*)d_in[1];
    const float* Wih  = (const float*)d_in[2];
    const float* Whh  = (const float*)d_in[3];
    const float* bih  = (const float*)d_in[4];
    const float* bhh  = (const float*)d_in[5];
    float* out = (float*)d_out;

    cudaFuncSetAttribute(gru_rec_kernel,
                         cudaFuncAttributeMaxDynamicSharedMemorySize,
                         SMEM_B_BYTES);

    dim3 gridA(G3 / 128, (Bsz * Ssz) / 128);
    gemm_gx_kernel<<<gridA, 256>>>(x, Wih, bih);

    gru_rec_kernel<<<Bsz, TPB_B, SMEM_B_BYTES>>>(mask, Whh, bhh, out);
}